// round 2
// baseline (speedup 1.0000x reference)
#include <cuda_runtime.h>
#include <math.h>

#define B_ 4
#define S_ 4096
#define H_ 2048
#define E_ 16
#define ED_ 512

// ---------------- scratch (device globals; no allocation allowed) ----------------
__device__ float g_acc[B_ * H_];   // sum_s (x-mu)*rstd
__device__ float g_qin[B_ * H_];   // query_input
__device__ float g_lf[E_ * H_];    // layer_features
__device__ float g_wsum[ED_];      // sum_i w_i * edge[i]
__device__ float g_q[B_ * H_];
__device__ float g_k[E_ * H_];
__device__ float g_att[B_ * E_];
__device__ float g_eb[E_];

// ---------------- K0: zero accumulator ----------------
__global__ void k_zero() {
    g_acc[blockIdx.x * 256 + threadIdx.x] = 0.0f;
}

// ---------------- K1: fused LayerNorm + mean over S (single pass over 128MB) ----
// grid 256 = 4 batches * 64 chunks; block 256 threads; 64 rows per block.
__global__ void k_ln_mean(const float* __restrict__ x) {
    int b = blockIdx.x >> 6;
    int c = blockIdx.x & 63;
    int tid = threadIdx.x;
    int lane = tid & 31, wid = tid >> 5;

    const float* base = x + ((size_t)(b * S_ + c * 64)) * H_;
    int o0 = tid * 4;
    int o1 = 1024 + tid * 4;

    float4 c0 = *(const float4*)(base + o0);
    float4 c1 = *(const float4*)(base + o1);

    float a0 = 0, a1 = 0, a2 = 0, a3 = 0, a4 = 0, a5 = 0, a6 = 0, a7 = 0;

    __shared__ float2 red[8];
    __shared__ float2 fin;

    for (int r = 0; r < 64; r++) {
        float4 n0, n1;
        if (r < 63) {
            const float* nb = base + (size_t)(r + 1) * H_;
            n0 = *(const float4*)(nb + o0);
            n1 = *(const float4*)(nb + o1);
        }
        float s  = c0.x + c0.y + c0.z + c0.w + c1.x + c1.y + c1.z + c1.w;
        float ss = c0.x*c0.x + c0.y*c0.y + c0.z*c0.z + c0.w*c0.w
                 + c1.x*c1.x + c1.y*c1.y + c1.z*c1.z + c1.w*c1.w;
        #pragma unroll
        for (int o = 16; o; o >>= 1) {
            s  += __shfl_xor_sync(0xffffffffu, s, o);
            ss += __shfl_xor_sync(0xffffffffu, ss, o);
        }
        if (lane == 0) red[wid] = make_float2(s, ss);
        __syncthreads();
        if (wid == 0) {
            float2 v = (lane < 8) ? red[lane] : make_float2(0.f, 0.f);
            #pragma unroll
            for (int o = 4; o; o >>= 1) {
                v.x += __shfl_xor_sync(0xffffffffu, v.x, o);
                v.y += __shfl_xor_sync(0xffffffffu, v.y, o);
            }
            if (lane == 0) fin = v;
        }
        __syncthreads();
        float mu   = fin.x * (1.0f / (float)H_);
        float var  = fin.y * (1.0f / (float)H_) - mu * mu;
        float rstd = rsqrtf(var + 1e-5f);

        a0 += (c0.x - mu) * rstd;
        a1 += (c0.y - mu) * rstd;
        a2 += (c0.z - mu) * rstd;
        a3 += (c0.w - mu) * rstd;
        a4 += (c1.x - mu) * rstd;
        a5 += (c1.y - mu) * rstd;
        a6 += (c1.z - mu) * rstd;
        a7 += (c1.w - mu) * rstd;

        if (r < 63) { c0 = n0; c1 = n1; }
    }

    float* acc = g_acc + b * H_;
    atomicAdd(acc + o0 + 0, a0);
    atomicAdd(acc + o0 + 1, a1);
    atomicAdd(acc + o0 + 2, a2);
    atomicAdd(acc + o0 + 3, a3);
    atomicAdd(acc + o1 + 0, a4);
    atomicAdd(acc + o1 + 1, a5);
    atomicAdd(acc + o1 + 2, a6);
    atomicAdd(acc + o1 + 3, a7);
}

// ---------------- K2: prep qin, lf, wsum ----------------
// grid 21 blocks: 0..3 -> qin rows, 4..19 -> lf rows, 20 -> wsum
__global__ void k_prep(const float* __restrict__ lemb,
                       const float* __restrict__ cemb,
                       const float* __restrict__ gamma,
                       const float* __restrict__ beta,
                       const float* __restrict__ edge,
                       const int* __restrict__ curp,
                       const int* __restrict__ avail) {
    int cur = curp ? curp[0] : 0;
    int bid = blockIdx.x, tid = threadIdx.x;
    if (bid < 4) {
        int b = bid;
        for (int h = tid; h < H_; h += 256)
            g_qin[b * H_ + h] = lemb[cur * H_ + h]
                              + gamma[h] * (g_acc[b * H_ + h] * (1.0f / (float)S_))
                              + beta[h];
    } else if (bid < 20) {
        int e = bid - 4;
        for (int h = tid; h < H_; h += 256)
            g_lf[e * H_ + h] = lemb[e * H_ + h] + cemb[e * H_ + h];
    } else {
        for (int hh = tid; hh < ED_; hh += 256) {
            float s = 0.0f;
            #pragma unroll
            for (int i = 0; i < E_; i++) {
                int d = i - cur; if (d < 0) d = -d;
                if (avail[i] != 0 && i != cur) {
                    float w = 1.0f / (float)(d > 1 ? d : 1);
                    s += w * edge[i * ED_ + hh];
                }
            }
            g_wsum[hh] = s;
        }
    }
}

// ---------------- K3: fused q/k GEMV ----------------
// grid 128 blocks, 256 threads, 32KB dynamic smem.
// Each block owns 16 output columns; computes both k (N=16) and q (N=4).
template <int N, int JW>
__device__ __forceinline__ void gemv_body(const float* __restrict__ A,
                                          const float* __restrict__ W,
                                          const float* __restrict__ bias,
                                          float* __restrict__ OUT, int jbase) {
    extern __shared__ float As[];  // [16][512] chunk of A
    int tid = threadIdx.x;
    int hs = tid & 31, jg = tid >> 5;  // 8 warps, each owns JW columns
    int j0 = jbase + jg * JW;

    float p[N][JW];
    #pragma unroll
    for (int e = 0; e < N; e++)
        #pragma unroll
        for (int jj = 0; jj < JW; jj++) p[e][jj] = 0.0f;

    for (int chunk = 0; chunk < 4; chunk++) {
        __syncthreads();
        for (int i = tid; i < N * 128; i += 256) {
            int e = i >> 7, h4 = i & 127;
            *(float4*)&As[e * 512 + h4 * 4] =
                *(const float4*)&A[e * H_ + chunk * 512 + h4 * 4];
        }
        __syncthreads();
        const float* Wc = W + chunk * 512;
        #pragma unroll 4
        for (int ii = 0; ii < 16; ii++) {
            int h = hs + 32 * ii;
            float w[JW];
            #pragma unroll
            for (int jj = 0; jj < JW; jj++)
                w[jj] = Wc[(size_t)(j0 + jj) * H_ + h];
            #pragma unroll
            for (int e = 0; e < N; e++) {
                float a = As[e * 512 + h];
                #pragma unroll
                for (int jj = 0; jj < JW; jj++) p[e][jj] += a * w[jj];
            }
        }
    }
    #pragma unroll
    for (int e = 0; e < N; e++)
        #pragma unroll
        for (int jj = 0; jj < JW; jj++) {
            float v = p[e][jj];
            #pragma unroll
            for (int o = 16; o; o >>= 1) v += __shfl_xor_sync(0xffffffffu, v, o);
            p[e][jj] = v;
        }
    if (hs == 0) {
        #pragma unroll
        for (int e = 0; e < N; e++)
            #pragma unroll
            for (int jj = 0; jj < JW; jj++)
                OUT[e * H_ + j0 + jj] = p[e][jj] + bias[j0 + jj];
    }
}

__global__ void k_gemv(const float* __restrict__ Wq, const float* __restrict__ bq,
                       const float* __restrict__ Wk, const float* __restrict__ bk) {
    int jbase = blockIdx.x * 16;
    gemv_body<E_, 2>(g_lf, Wk, bk, g_k, jbase);
    gemv_body<B_, 2>(g_qin, Wq, bq, g_q, jbase);
}

// ---------------- K4: attention dots + edge bias ----------------
// grid 80: blocks 0..63 -> attention[b][e]; 64..79 -> edge_bias[j]
__global__ void k_att(const float* __restrict__ edge) {
    __shared__ float red[8];
    int bid = blockIdx.x, tid = threadIdx.x;
    int lane = tid & 31, wid = tid >> 5;
    float s = 0.0f;
    if (bid < 64) {
        int b = bid >> 4, e = bid & 15;
        const float* q = g_q + b * H_;
        const float* k = g_k + e * H_;
        for (int h = tid; h < H_; h += 256) s += q[h] * k[h];
    } else {
        int j = bid - 64;
        for (int hh = tid; hh < ED_; hh += 256) s += g_wsum[hh] * edge[j * ED_ + hh];
    }
    #pragma unroll
    for (int o = 16; o; o >>= 1) s += __shfl_xor_sync(0xffffffffu, s, o);
    if (lane == 0) red[wid] = s;
    __syncthreads();
    if (tid == 0) {
        float t = 0.0f;
        #pragma unroll
        for (int w = 0; w < 8; w++) t += red[w];
        if (bid < 64) g_att[bid] = t * 0.022097086912079612f;  // 1/sqrt(2048)
        else          g_eb[bid - 64] = t;
    }
}

// ---------------- K5: scores, softmax, KL, argmax, output ----------------
__global__ void k_final(const float* __restrict__ spatial,
                        const int* __restrict__ curp,
                        const int* __restrict__ avail,
                        float* __restrict__ out, int out_size) {
    int tid = threadIdx.x;
    int lane = tid & 31, b = tid >> 5;  // 4 warps, one per batch
    int cur = curp ? curp[0] : 0;

    __shared__ float sprobs[64];
    __shared__ float klpart[4];
    __shared__ float s_loss;
    __shared__ int   sidx;

    float navail = 0.0f;
    #pragma unroll
    for (int i = 0; i < E_; i++) navail += (avail[i] != 0) ? 1.0f : 0.0f;
    float t = 1.0f / navail;

    float s = -1e9f;
    if (lane < 16) {
        int e = lane;
        int d = e - cur; if (d < 0) d = -d;
        float sc = g_att[b * E_ + e] + spatial[d] + g_eb[e];
        s = (avail[e] != 0) ? sc : -1e9f;
    }
    // softmax over 16 lanes (lanes >=16 hold -1e9 / contribute 0)
    float m = s;
    #pragma unroll
    for (int o = 16; o; o >>= 1) m = fmaxf(m, __shfl_xor_sync(0xffffffffu, m, o));
    float ex = (lane < 16) ? expf(s - m) : 0.0f;
    float sum = ex;
    #pragma unroll
    for (int o = 16; o; o >>= 1) sum += __shfl_xor_sync(0xffffffffu, sum, o);
    float prob = (lane < 16) ? ex / sum : 0.0f;
    if (lane < 16) sprobs[b * 16 + lane] = prob;

    float term = (lane < 16) ? t * (logf(t) - logf(fmaxf(prob, 1e-10f))) : 0.0f;
    float ksum = term;
    #pragma unroll
    for (int o = 16; o; o >>= 1) ksum += __shfl_xor_sync(0xffffffffu, ksum, o);
    if (lane == 0) klpart[b] = ksum;

    if (b == 0) {
        float pm = prob;
        #pragma unroll
        for (int o = 16; o; o >>= 1) pm = fmaxf(pm, __shfl_xor_sync(0xffffffffu, pm, o));
        unsigned ball = __ballot_sync(0xffffffffu, (lane < 16) && (prob == pm));
        if (lane == 0) sidx = __ffs(ball) - 1;
    }
    __syncthreads();
    if (tid == 0)
        s_loss = (klpart[0] + klpart[1] + klpart[2] + klpart[3]) * 0.25f * 0.01f;
    __syncthreads();

    // output: (loss, probs[64], next_idx) flattened, with defensive layouts
    if (out_size == 64) {
        if (tid < 64) out[tid] = sprobs[tid];
    } else {
        if (tid == 0 && out_size >= 1) out[0] = s_loss;
        if (tid < 64 && 1 + tid < out_size) out[1 + tid] = sprobs[tid];
        if (tid == 0 && out_size >= 66) out[65] = (float)sidx;
        for (int i = 66 + tid; i < out_size; i += 128) out[i] = 0.0f;
    }
}

// ---------------- host ----------------
extern "C" void kernel_launch(void* const* d_in, const int* in_sizes, int n_in,
                              void* d_out, int out_size) {
    const float* hidden  = (const float*)d_in[0];
    const float* lemb    = (const float*)d_in[1];
    const float* cemb    = (const float*)d_in[2];
    const float* spatial = (const float*)d_in[3];
    const float* edge    = (const float*)d_in[4];
    const float* gamma   = (const float*)d_in[5];
    const float* beta    = (const float*)d_in[6];
    const float* Wq      = (const float*)d_in[7];
    const float* bq      = (const float*)d_in[8];
    const float* Wk      = (const float*)d_in[9];
    const float* bk      = (const float*)d_in[10];
    // d_in[11], d_in[12] = Wv, bv : dead in the reference, never touched.

    const int* curp  = nullptr;
    const int* avail = nullptr;
    if (n_in >= 15) {
        curp  = (const int*)d_in[13];
        avail = (const int*)d_in[14];
    } else {
        avail = (const int*)d_in[n_in - 1];
    }

    k_zero<<<32, 256>>>();
    k_ln_mean<<<256, 256>>>(hidden);
    k_prep<<<21, 256>>>(lemb, cemb, gamma, beta, edge, curp, avail);
    k_gemv<<<128, 256, 16 * 512 * sizeof(float)>>>(Wq, bq, Wk, bk);
    k_att<<<80, 256>>>(edge);
    k_final<<<1, 128>>>(spatial, curp, avail, (float*)d_out, out_size);
}

// round 3
// speedup vs baseline: 1.7986x; 1.7986x over previous
#include <cuda_runtime.h>
#include <math.h>

#define B_ 4
#define S_ 4096
#define H_ 2048
#define E_ 16
#define ED_ 512

// ---------------- scratch (device globals; no allocation allowed) ----------------
__device__ float g_acc[B_ * H_];   // sum_s (x-mu)*rstd
__device__ float g_qin[B_ * H_];   // query_input
__device__ float g_lf[E_ * H_];    // layer_features
__device__ float g_wsum[ED_];      // sum_i w_i * edge[i]
__device__ float g_q[B_ * H_];     // seeded with bq, accumulated by k_gemv
__device__ float g_k[E_ * H_];     // seeded with bk, accumulated by k_gemv
__device__ float g_att[B_ * E_];
__device__ float g_eb[E_];

// ---------------- K0: init accumulators (zero g_acc, seed biases) ----------------
// grid 192*256 = 49152 = 8192 (g_acc) + 32768 (g_k) + 8192 (g_q)
__global__ void k_init(const float* __restrict__ bq, const float* __restrict__ bk) {
    int i = blockIdx.x * 256 + threadIdx.x;
    if (i < B_ * H_) {
        g_acc[i] = 0.0f;
    } else if (i < B_ * H_ + E_ * H_) {
        int j = i - B_ * H_;
        g_k[j] = bk[j & (H_ - 1)];
    } else {
        int j = i - B_ * H_ - E_ * H_;
        g_q[j] = bq[j & (H_ - 1)];
    }
}

// ---------------- K1: fused LayerNorm + mean over S, warp-per-row ----------------
// grid 128 = 4 batches * 32 blocks; block 256 (8 warps); warp handles 16 rows.
// Each lane loads 16 float4 (full 2048-elem row split across the warp), keeps
// them in registers, reduces stats with shuffles only (no block barriers per
// row), and accumulates (x-mu)*rstd into 64 per-lane registers.
__global__ void __launch_bounds__(256, 1) k_ln_mean(const float* __restrict__ x) {
    int b = blockIdx.x >> 5;          // 32 blocks per batch
    int blk = blockIdx.x & 31;
    int tid = threadIdx.x;
    int lane = tid & 31, wid = tid >> 5;

    int row0 = blk * 128 + wid * 16;  // this warp's first row
    const float* xb = x + ((size_t)b * S_ + row0) * H_;

    float4 acc[16];
    #pragma unroll
    for (int k = 0; k < 16; k++) acc[k] = make_float4(0.f, 0.f, 0.f, 0.f);

    for (int r = 0; r < 16; r++) {
        const float4* row = (const float4*)(xb + (size_t)r * H_);
        float4 v[16];
        float s = 0.0f, ss = 0.0f;
        #pragma unroll
        for (int k = 0; k < 16; k++) {
            v[k] = row[k * 32 + lane];
            s  += v[k].x + v[k].y + v[k].z + v[k].w;
            ss += v[k].x * v[k].x + v[k].y * v[k].y
                + v[k].z * v[k].z + v[k].w * v[k].w;
        }
        #pragma unroll
        for (int o = 16; o; o >>= 1) {
            s  += __shfl_xor_sync(0xffffffffu, s, o);
            ss += __shfl_xor_sync(0xffffffffu, ss, o);
        }
        float mu   = s * (1.0f / (float)H_);
        float var  = ss * (1.0f / (float)H_) - mu * mu;
        float rstd = rsqrtf(var + 1e-5f);
        #pragma unroll
        for (int k = 0; k < 16; k++) {
            acc[k].x += (v[k].x - mu) * rstd;
            acc[k].y += (v[k].y - mu) * rstd;
            acc[k].z += (v[k].z - mu) * rstd;
            acc[k].w += (v[k].w - mu) * rstd;
        }
    }

    // block-level merge: sequential warp accumulation into smem (8 barriers total)
    __shared__ float sm[H_];
    for (int w = 0; w < 8; w++) {
        if (wid == w) {
            #pragma unroll
            for (int k = 0; k < 16; k++) {
                float4* p = (float4*)&sm[k * 128 + lane * 4];
                if (w == 0) {
                    *p = acc[k];
                } else {
                    float4 t = *p;
                    t.x += acc[k].x; t.y += acc[k].y;
                    t.z += acc[k].z; t.w += acc[k].w;
                    *p = t;
                }
            }
        }
        __syncthreads();
    }

    float* g = g_acc + b * H_;
    #pragma unroll
    for (int t = 0; t < 8; t++)
        atomicAdd(g + tid * 8 + t, sm[tid * 8 + t]);
}

// ---------------- K2: prep qin, lf, wsum ----------------
// grid 21 blocks: 0..3 -> qin rows, 4..19 -> lf rows, 20 -> wsum
__global__ void k_prep(const float* __restrict__ lemb,
                       const float* __restrict__ cemb,
                       const float* __restrict__ gamma,
                       const float* __restrict__ beta,
                       const float* __restrict__ edge,
                       const int* __restrict__ curp,
                       const int* __restrict__ avail) {
    int cur = curp ? curp[0] : 0;
    int bid = blockIdx.x, tid = threadIdx.x;
    if (bid < 4) {
        int b = bid;
        for (int h = tid; h < H_; h += 256)
            g_qin[b * H_ + h] = lemb[cur * H_ + h]
                              + gamma[h] * (g_acc[b * H_ + h] * (1.0f / (float)S_))
                              + beta[h];
    } else if (bid < 20) {
        int e = bid - 4;
        for (int h = tid; h < H_; h += 256)
            g_lf[e * H_ + h] = lemb[e * H_ + h] + cemb[e * H_ + h];
    } else {
        for (int hh = tid; hh < ED_; hh += 256) {
            float s = 0.0f;
            #pragma unroll
            for (int i = 0; i < E_; i++) {
                int d = i - cur; if (d < 0) d = -d;
                if (avail[i] != 0 && i != cur) {
                    float w = 1.0f / (float)(d > 1 ? d : 1);
                    s += w * edge[i * ED_ + hh];
                }
            }
            g_wsum[hh] = s;
        }
    }
}

// ---------------- K3: split-K GEMV, warp-per-(column, chunk) ----------------
// CH=512, NC=4 chunks over H. 8 columns per block (warp per column).
// Wk part: 256 jgroups * 4 chunks = 1024 blocks (N=16 rows of A).
// Wq part: 1024 blocks (N=4). Partials accumulated with atomicAdd onto
// bias-seeded g_k/g_q.
template <int N>
__device__ __forceinline__ void gemv_part(const float* __restrict__ W,
                                          const float* __restrict__ A,
                                          float* __restrict__ OUT, int idx) {
    extern __shared__ float As[];   // [N][512]
    int jg = idx >> 2;              // 0..255
    int c  = idx & 3;               // chunk
    int tid = threadIdx.x;
    int lane = tid & 31, w = tid >> 5;
    int j = jg * 8 + w;

    // issue W loads early (independent of smem staging)
    const float4* Wr = (const float4*)(W + (size_t)j * H_ + c * 512);
    float4 wv[4];
    #pragma unroll
    for (int t = 0; t < 4; t++) wv[t] = Wr[t * 32 + lane];

    // stage A chunk into smem
    const float4* A4 = (const float4*)A;
    float4* As4 = (float4*)As;
    #pragma unroll
    for (int i = tid; i < N * 128; i += 256) {
        int e = i >> 7, p = i & 127;
        As4[e * 128 + p] = A4[e * 512 + c * 128 + p];
    }
    __syncthreads();

    float acc[N];
    #pragma unroll
    for (int e = 0; e < N; e++) acc[e] = 0.0f;

    #pragma unroll
    for (int e = 0; e < N; e++) {
        #pragma unroll
        for (int t = 0; t < 4; t++) {
            float4 a = As4[e * 128 + t * 32 + lane];
            acc[e] += wv[t].x * a.x + wv[t].y * a.y
                    + wv[t].z * a.z + wv[t].w * a.w;
        }
    }
    #pragma unroll
    for (int e = 0; e < N; e++) {
        #pragma unroll
        for (int o = 16; o; o >>= 1)
            acc[e] += __shfl_xor_sync(0xffffffffu, acc[e], o);
    }
    if (lane == 0) {
        #pragma unroll
        for (int e = 0; e < N; e++)
            atomicAdd(&OUT[e * H_ + j], acc[e]);
    }
}

__global__ void k_gemv(const float* __restrict__ Wq, const float* __restrict__ Wk) {
    int bid = blockIdx.x;
    if (bid < 1024) gemv_part<E_>(Wk, g_lf, g_k, bid);
    else            gemv_part<B_>(Wq, g_qin, g_q, bid - 1024);
}

// ---------------- K4: attention dots + edge bias ----------------
// grid 80: blocks 0..63 -> attention[b][e]; 64..79 -> edge_bias[j]
__global__ void k_att(const float* __restrict__ edge) {
    __shared__ float red[8];
    int bid = blockIdx.x, tid = threadIdx.x;
    int lane = tid & 31, wid = tid >> 5;
    float s = 0.0f;
    if (bid < 64) {
        int b = bid >> 4, e = bid & 15;
        const float* q = g_q + b * H_;
        const float* k = g_k + e * H_;
        for (int h = tid; h < H_; h += 256) s += q[h] * k[h];
    } else {
        int j = bid - 64;
        for (int hh = tid; hh < ED_; hh += 256) s += g_wsum[hh] * edge[j * ED_ + hh];
    }
    #pragma unroll
    for (int o = 16; o; o >>= 1) s += __shfl_xor_sync(0xffffffffu, s, o);
    if (lane == 0) red[wid] = s;
    __syncthreads();
    if (tid == 0) {
        float t = 0.0f;
        #pragma unroll
        for (int w = 0; w < 8; w++) t += red[w];
        if (bid < 64) g_att[bid] = t * 0.022097086912079612f;  // 1/sqrt(2048)
        else          g_eb[bid - 64] = t;
    }
}

// ---------------- K5: scores, softmax, KL, argmax, output ----------------
__global__ void k_final(const float* __restrict__ spatial,
                        const int* __restrict__ curp,
                        const int* __restrict__ avail,
                        float* __restrict__ out, int out_size) {
    int tid = threadIdx.x;
    int lane = tid & 31, b = tid >> 5;  // 4 warps, one per batch
    int cur = curp ? curp[0] : 0;

    __shared__ float sprobs[64];
    __shared__ float klpart[4];
    __shared__ float s_loss;
    __shared__ int   sidx;

    float navail = 0.0f;
    #pragma unroll
    for (int i = 0; i < E_; i++) navail += (avail[i] != 0) ? 1.0f : 0.0f;
    float t = 1.0f / navail;

    float s = -1e9f;
    if (lane < 16) {
        int e = lane;
        int d = e - cur; if (d < 0) d = -d;
        float sc = g_att[b * E_ + e] + spatial[d] + g_eb[e];
        s = (avail[e] != 0) ? sc : -1e9f;
    }
    float m = s;
    #pragma unroll
    for (int o = 16; o; o >>= 1) m = fmaxf(m, __shfl_xor_sync(0xffffffffu, m, o));
    float ex = (lane < 16) ? expf(s - m) : 0.0f;
    float sum = ex;
    #pragma unroll
    for (int o = 16; o; o >>= 1) sum += __shfl_xor_sync(0xffffffffu, sum, o);
    float prob = (lane < 16) ? ex / sum : 0.0f;
    if (lane < 16) sprobs[b * 16 + lane] = prob;

    float term = (lane < 16) ? t * (logf(t) - logf(fmaxf(prob, 1e-10f))) : 0.0f;
    float ksum = term;
    #pragma unroll
    for (int o = 16; o; o >>= 1) ksum += __shfl_xor_sync(0xffffffffu, ksum, o);
    if (lane == 0) klpart[b] = ksum;

    if (b == 0) {
        float pm = prob;
        #pragma unroll
        for (int o = 16; o; o >>= 1) pm = fmaxf(pm, __shfl_xor_sync(0xffffffffu, pm, o));
        unsigned ball = __ballot_sync(0xffffffffu, (lane < 16) && (prob == pm));
        if (lane == 0) sidx = __ffs(ball) - 1;
    }
    __syncthreads();
    if (tid == 0)
        s_loss = (klpart[0] + klpart[1] + klpart[2] + klpart[3]) * 0.25f * 0.01f;
    __syncthreads();

    if (out_size == 64) {
        if (tid < 64) out[tid] = sprobs[tid];
    } else {
        if (tid == 0 && out_size >= 1) out[0] = s_loss;
        if (tid < 64 && 1 + tid < out_size) out[1 + tid] = sprobs[tid];
        if (tid == 0 && out_size >= 66) out[65] = (float)sidx;
        for (int i = 66 + tid; i < out_size; i += 128) out[i] = 0.0f;
    }
}

// ---------------- host ----------------
extern "C" void kernel_launch(void* const* d_in, const int* in_sizes, int n_in,
                              void* d_out, int out_size) {
    const float* hidden  = (const float*)d_in[0];
    const float* lemb    = (const float*)d_in[1];
    const float* cemb    = (const float*)d_in[2];
    const float* spatial = (const float*)d_in[3];
    const float* edge    = (const float*)d_in[4];
    const float* gamma   = (const float*)d_in[5];
    const float* beta    = (const float*)d_in[6];
    const float* Wq      = (const float*)d_in[7];
    const float* bq      = (const float*)d_in[8];
    const float* Wk      = (const float*)d_in[9];
    const float* bk      = (const float*)d_in[10];
    // d_in[11], d_in[12] = Wv, bv : dead in the reference, never touched.

    const int* curp  = nullptr;
    const int* avail = nullptr;
    if (n_in >= 15) {
        curp  = (const int*)d_in[13];
        avail = (const int*)d_in[14];
    } else {
        avail = (const int*)d_in[n_in - 1];
    }

    k_init<<<192, 256>>>(bq, bk);
    k_ln_mean<<<128, 256>>>(hidden);
    k_prep<<<21, 256>>>(lemb, cemb, gamma, beta, edge, curp, avail);
    k_gemv<<<2048, 256, 16 * 512 * sizeof(float)>>>(Wq, Wk);
    k_att<<<80, 256>>>(edge);
    k_final<<<1, 128>>>(spatial, curp, avail, (float*)d_out, out_size);
}

// round 5
// speedup vs baseline: 2.2271x; 1.2382x over previous
#include <cuda_runtime.h>
#include <math.h>

#define B_ 4
#define S_ 4096
#define H_ 2048
#define E_ 16
#define ED_ 512

// ---------------- scratch ----------------
__device__ float g_acc[B_ * H_];   // sum_s (x-mu)*rstd
__device__ float g_q[B_ * H_];     // seeded with bq, accumulated by k_gemv
__device__ float g_k[E_ * H_];     // seeded with bk, accumulated by k_gemv
__device__ float g_att[B_ * E_];
__device__ float g_eb[E_];

// ---------------- K0: init (zero g_acc, seed biases) ----------------
// 192*256 = 49152 = 8192 (g_acc) + 32768 (g_k) + 8192 (g_q)
__global__ void k_init(const float* __restrict__ bq, const float* __restrict__ bk) {
    int i = blockIdx.x * 256 + threadIdx.x;
    if (i < B_ * H_) {
        g_acc[i] = 0.0f;
    } else if (i < B_ * H_ + E_ * H_) {
        int j = i - B_ * H_;
        g_k[j] = bk[j & (H_ - 1)];
    } else {
        int j = i - B_ * H_ - E_ * H_;
        g_q[j] = bq[j & (H_ - 1)];
    }
}

// ---------------- K1: fused LayerNorm + mean over S ----------------
// grid 256 = 4 batches * 64 blocks; 256 threads = 8 warps = 4 warp-pairs.
// A warp-pair owns a row: each warp covers 1024 columns (8 float4/lane).
// Next-row loads are prefetched while the current row reduces, so DRAM
// requests stay continuously in flight. Stats joined across the pair via a
// tiny double-buffered smem exchange (1 barrier per row).
__global__ void __launch_bounds__(256, 2) k_ln_mean(const float* __restrict__ x) {
    int b   = blockIdx.x >> 6;      // 64 blocks per batch
    int blk = blockIdx.x & 63;
    int tid = threadIdx.x;
    int lane = tid & 31, wid = tid >> 5;
    int pair = wid >> 1, half = wid & 1;

    int row0 = blk * 64 + pair * 16;    // this pair's first row
    const float* xb = x + ((size_t)b * S_ + row0) * H_ + half * 1024;

    __shared__ float2 st[2][4][2];      // [buf][pair][half]
    __shared__ float sm[H_];

    float4 v[8], vn[8], acc[8];
    #pragma unroll
    for (int k = 0; k < 8; k++) acc[k] = make_float4(0.f, 0.f, 0.f, 0.f);

    {
        const float4* row = (const float4*)xb;
        #pragma unroll
        for (int k = 0; k < 8; k++) v[k] = __ldcs(&row[k * 32 + lane]);
    }

    for (int r = 0; r < 16; r++) {
        if (r < 15) {
            const float4* nr = (const float4*)(xb + (size_t)(r + 1) * H_);
            #pragma unroll
            for (int k = 0; k < 8; k++) vn[k] = __ldcs(&nr[k * 32 + lane]);
        }
        float s = 0.f, ss = 0.f;
        #pragma unroll
        for (int k = 0; k < 8; k++) {
            s  += v[k].x + v[k].y + v[k].z + v[k].w;
            ss += v[k].x * v[k].x + v[k].y * v[k].y
                + v[k].z * v[k].z + v[k].w * v[k].w;
        }
        #pragma unroll
        for (int o = 16; o; o >>= 1) {
            s  += __shfl_xor_sync(0xffffffffu, s, o);
            ss += __shfl_xor_sync(0xffffffffu, ss, o);
        }
        if (lane == 0) st[r & 1][pair][half] = make_float2(s, ss);
        __syncthreads();
        float2 oth = st[r & 1][pair][half ^ 1];
        s += oth.x; ss += oth.y;

        float mu   = s * (1.0f / (float)H_);
        float var  = ss * (1.0f / (float)H_) - mu * mu;
        float rstd = rsqrtf(var + 1e-5f);
        #pragma unroll
        for (int k = 0; k < 8; k++) {
            acc[k].x += (v[k].x - mu) * rstd;
            acc[k].y += (v[k].y - mu) * rstd;
            acc[k].z += (v[k].z - mu) * rstd;
            acc[k].w += (v[k].w - mu) * rstd;
        }
        #pragma unroll
        for (int k = 0; k < 8; k++) v[k] = vn[k];
    }

    // merge the 4 pairs' accumulators (per column half) in smem
    float* smh = sm + half * 1024;
    for (int p = 0; p < 4; p++) {
        if (pair == p) {
            #pragma unroll
            for (int k = 0; k < 8; k++) {
                float4* d = (float4*)&smh[k * 128 + lane * 4];
                if (p == 0) {
                    *d = acc[k];
                } else {
                    float4 t = *d;
                    t.x += acc[k].x; t.y += acc[k].y;
                    t.z += acc[k].z; t.w += acc[k].w;
                    *d = t;
                }
            }
        }
        __syncthreads();
    }

    float* g = g_acc + b * H_;
    #pragma unroll
    for (int t = 0; t < 8; t++)
        atomicAdd(g + tid * 8 + t, sm[tid * 8 + t]);
}

// ---------------- K2: split-K GEMV, 4 columns per warp ----------------
// 512 blocks: bid<256 -> Wk part (N=16 rows), else Wq part (N=4 rows).
// Per part: 64 col-groups (32 cols each, warp handles 4) x 4 H-chunks of 512.
// A (lf / qin) is computed on the fly during smem staging.
template <int N>
__device__ __forceinline__ void gemv_compute(const float* __restrict__ W,
                                             float* __restrict__ OUT,
                                             const float4* __restrict__ As4,
                                             int cg, int c, int lane, int w) {
    int j0 = cg * 32 + w * 4;
    float acc[N][4];
    #pragma unroll
    for (int e = 0; e < N; e++)
        #pragma unroll
        for (int jj = 0; jj < 4; jj++) acc[e][jj] = 0.0f;

    const float4* W4 = (const float4*)W;
    #pragma unroll
    for (int t = 0; t < 4; t++) {
        float4 wv[4];
        #pragma unroll
        for (int jj = 0; jj < 4; jj++)
            wv[jj] = W4[(size_t)(j0 + jj) * 512 + c * 128 + t * 32 + lane];
        #pragma unroll
        for (int e = 0; e < N; e++) {
            float4 a = As4[e * 128 + t * 32 + lane];
            #pragma unroll
            for (int jj = 0; jj < 4; jj++) {
                acc[e][jj] = fmaf(a.x, wv[jj].x,
                             fmaf(a.y, wv[jj].y,
                             fmaf(a.z, wv[jj].z,
                             fmaf(a.w, wv[jj].w, acc[e][jj]))));
            }
        }
    }
    #pragma unroll
    for (int e = 0; e < N; e++)
        #pragma unroll
        for (int jj = 0; jj < 4; jj++) {
            float vsum = acc[e][jj];
            #pragma unroll
            for (int o = 16; o; o >>= 1)
                vsum += __shfl_xor_sync(0xffffffffu, vsum, o);
            acc[e][jj] = vsum;
        }
    if (lane == 0) {
        #pragma unroll
        for (int e = 0; e < N; e++)
            #pragma unroll
            for (int jj = 0; jj < 4; jj++)
                atomicAdd(&OUT[e * H_ + j0 + jj], acc[e][jj]);
    }
}

__global__ void __launch_bounds__(256) k_gemv(const float* __restrict__ Wq,
                                              const float* __restrict__ Wk,
                                              const float* __restrict__ lemb,
                                              const float* __restrict__ cemb,
                                              const float* __restrict__ gamma,
                                              const float* __restrict__ beta,
                                              const int* __restrict__ curp) {
    extern __shared__ float4 As4[];   // [N][128] float4 = N x 512 floats
    int bid = blockIdx.x;
    int tid = threadIdx.x, lane = tid & 31, w = tid >> 5;

    if (bid < 256) {
        int cg = bid >> 2, c = bid & 3;
        const float4* l4 = (const float4*)lemb;
        const float4* c4 = (const float4*)cemb;
        #pragma unroll
        for (int i = tid; i < 16 * 128; i += 256) {
            int e = i >> 7, p = i & 127;
            float4 a = l4[e * 512 + c * 128 + p];
            float4 bb = c4[e * 512 + c * 128 + p];
            a.x += bb.x; a.y += bb.y; a.z += bb.z; a.w += bb.w;
            As4[i] = a;
        }
        __syncthreads();
        gemv_compute<E_>(Wk, g_k, As4, cg, c, lane, w);
    } else {
        bid -= 256;
        int cg = bid >> 2, c = bid & 3;
        int cur = curp ? curp[0] : 0;
        const float4* l4 = (const float4*)lemb + (size_t)cur * 512;
        const float4* g4 = (const float4*)gamma;
        const float4* b4 = (const float4*)beta;
        const float4* a4 = (const float4*)g_acc;
        #pragma unroll
        for (int i = tid; i < 4 * 128; i += 256) {
            int e = i >> 7, p = i & 127;
            int hp = c * 128 + p;
            float4 le = l4[hp], ga = g4[hp], be = b4[hp];
            float4 ac = a4[e * 512 + hp];
            float4 r;
            r.x = le.x + ga.x * (ac.x * (1.0f / (float)S_)) + be.x;
            r.y = le.y + ga.y * (ac.y * (1.0f / (float)S_)) + be.y;
            r.z = le.z + ga.z * (ac.z * (1.0f / (float)S_)) + be.z;
            r.w = le.w + ga.w * (ac.w * (1.0f / (float)S_)) + be.w;
            As4[i] = r;
        }
        __syncthreads();
        gemv_compute<B_>(Wq, g_q, As4, cg, c, lane, w);
    }
}

// ---------------- K3: attention dots + edge bias ----------------
// grid 80: blocks 0..63 -> attention[b][e]; 64..79 -> edge_bias[j] (wsum inline)
__global__ void k_att(const float* __restrict__ edge,
                      const int* __restrict__ curp,
                      const int* __restrict__ avail) {
    __shared__ float red[8];
    int bid = blockIdx.x, tid = threadIdx.x;
    int lane = tid & 31, wid = tid >> 5;
    float s = 0.0f;
    if (bid < 64) {
        int b = bid >> 4, e = bid & 15;
        const float* q = g_q + b * H_;
        const float* k = g_k + e * H_;
        for (int h = tid; h < H_; h += 256) s += q[h] * k[h];
    } else {
        int j = bid - 64;
        int cur = curp ? curp[0] : 0;
        float wgt[E_];
        #pragma unroll
        for (int i = 0; i < E_; i++) {
            int d = i - cur; if (d < 0) d = -d;
            float wi = 1.0f / (float)(d > 1 ? d : 1);
            wgt[i] = (avail[i] != 0 && i != cur) ? wi : 0.0f;
        }
        for (int hh = tid; hh < ED_; hh += 256) {
            float ws = 0.0f;
            #pragma unroll
            for (int i = 0; i < E_; i++) ws += wgt[i] * edge[i * ED_ + hh];
            s += ws * edge[j * ED_ + hh];
        }
    }
    #pragma unroll
    for (int o = 16; o; o >>= 1) s += __shfl_xor_sync(0xffffffffu, s, o);
    if (lane == 0) red[wid] = s;
    __syncthreads();
    if (tid == 0) {
        float t = 0.0f;
        #pragma unroll
        for (int w = 0; w < 8; w++) t += red[w];
        if (bid < 64) g_att[bid] = t * 0.022097086912079612f;  // 1/sqrt(2048)
        else          g_eb[bid - 64] = t;
    }
}

// ---------------- K4: scores, softmax, KL, argmax, output ----------------
__global__ void k_final(const float* __restrict__ spatial,
                        const int* __restrict__ curp,
                        const int* __restrict__ avail,
                        float* __restrict__ out, int out_size) {
    int tid = threadIdx.x;
    int lane = tid & 31, b = tid >> 5;  // 4 warps, one per batch
    int cur = curp ? curp[0] : 0;

    __shared__ float sprobs[64];
    __shared__ float klpart[4];
    __shared__ float s_loss;
    __shared__ int   sidx;

    float navail = 0.0f;
    #pragma unroll
    for (int i = 0; i < E_; i++) navail += (avail[i] != 0) ? 1.0f : 0.0f;
    float t = 1.0f / navail;

    float s = -1e9f;
    if (lane < 16) {
        int e = lane;
        int d = e - cur; if (d < 0) d = -d;
        float sc = g_att[b * E_ + e] + spatial[d] + g_eb[e];
        s = (avail[e] != 0) ? sc : -1e9f;
    }
    float m = s;
    #pragma unroll
    for (int o = 16; o; o >>= 1) m = fmaxf(m, __shfl_xor_sync(0xffffffffu, m, o));
    float ex = (lane < 16) ? expf(s - m) : 0.0f;
    float sum = ex;
    #pragma unroll
    for (int o = 16; o; o >>= 1) sum += __shfl_xor_sync(0xffffffffu, sum, o);
    float prob = (lane < 16) ? ex / sum : 0.0f;
    if (lane < 16) sprobs[b * 16 + lane] = prob;

    float term = (lane < 16) ? t * (logf(t) - logf(fmaxf(prob, 1e-10f))) : 0.0f;
    float ksum = term;
    #pragma unroll
    for (int o = 16; o; o >>= 1) ksum += __shfl_xor_sync(0xffffffffu, ksum, o);
    if (lane == 0) klpart[b] = ksum;

    if (b == 0) {
        float pm = prob;
        #pragma unroll
        for (int o = 16; o; o >>= 1) pm = fmaxf(pm, __shfl_xor_sync(0xffffffffu, pm, o));
        unsigned ball = __ballot_sync(0xffffffffu, (lane < 16) && (prob == pm));
        if (lane == 0) sidx = __ffs(ball) - 1;
    }
    __syncthreads();
    if (tid == 0)
        s_loss = (klpart[0] + klpart[1] + klpart[2] + klpart[3]) * 0.25f * 0.01f;
    __syncthreads();

    if (out_size == 64) {
        if (tid < 64) out[tid] = sprobs[tid];
    } else {
        if (tid == 0 && out_size >= 1) out[0] = s_loss;
        if (tid < 64 && 1 + tid < out_size) out[1 + tid] = sprobs[tid];
        if (tid == 0 && out_size >= 66) out[65] = (float)sidx;
        for (int i = 66 + tid; i < out_size; i += 128) out[i] = 0.0f;
    }
}

// ---------------- host ----------------
extern "C" void kernel_launch(void* const* d_in, const int* in_sizes, int n_in,
                              void* d_out, int out_size) {
    const float* hidden  = (const float*)d_in[0];
    const float* lemb    = (const float*)d_in[1];
    const float* cemb    = (const float*)d_in[2];
    const float* spatial = (const float*)d_in[3];
    const float* edge    = (const float*)d_in[4];
    const float* gamma   = (const float*)d_in[5];
    const float* beta    = (const float*)d_in[6];
    const float* Wq      = (const float*)d_in[7];
    const float* bq      = (const float*)d_in[8];
    const float* Wk      = (const float*)d_in[9];
    const float* bk      = (const float*)d_in[10];
    // d_in[11], d_in[12] = Wv, bv : dead in the reference, never touched.

    const int* curp  = nullptr;
    const int* avail = nullptr;
    if (n_in >= 15) {
        curp  = (const int*)d_in[13];
        avail = (const int*)d_in[14];
    } else {
        avail = (const int*)d_in[n_in - 1];
    }

    k_init<<<192, 256>>>(bq, bk);
    k_ln_mean<<<256, 256>>>(hidden);
    k_gemv<<<512, 256, 16 * 512 * sizeof(float)>>>(Wq, Wk, lemb, cemb,
                                                   gamma, beta, curp);
    k_att<<<80, 256>>>(edge, curp, avail);
    k_final<<<1, 128>>>(spatial, curp, avail, (float*)d_out, out_size);
}